// round 6
// baseline (speedup 1.0000x reference)
#include <cuda_runtime.h>
#include <cuda_bf16.h>
#include <math_constants.h>
#include <cstdint>

#define S_ 16384
#define K_ 4096
#define D_ 64
#define TEMP_ 50.0f
#define MAXEFF_ 5000.0f

// ---------------- scratch ----------------
__device__ float        g_aff[(size_t)S_ * K_];
__device__ unsigned int g_pmax[S_];
__device__ unsigned int g_nmax[S_];

__device__ __forceinline__ unsigned int encf(float f) {
    unsigned int u = __float_as_uint(f);
    return (u & 0x80000000u) ? ~u : (u | 0x80000000u);
}
__device__ __forceinline__ float decf(unsigned int u) {
    return (u & 0x80000000u) ? __uint_as_float(u ^ 0x80000000u)
                             : __uint_as_float(~u);
}

// ---------------- tf32 helpers (sm_80-compatible PTX only) ----------------
__device__ __forceinline__ float tf32r(float x) {
    uint32_t u;
    asm("cvt.rna.tf32.f32 %0, %1;" : "=r"(u) : "f"(x));
    return __uint_as_float(u);
}
__device__ __forceinline__ void split1(float x, float& h, float& l) {
    h = tf32r(x);
    l = tf32r(x - h);
}
__device__ __forceinline__ void split4(float4 v, float4& h, float4& l) {
    split1(v.x, h.x, l.x); split1(v.y, h.y, l.y);
    split1(v.z, h.z, l.z); split1(v.w, h.w, l.w);
}

// D(16x8,f32) += A(16x8,tf32,row) * B(8x8,tf32,col)
__device__ __forceinline__ void mma8(float* c, const uint32_t* a,
                                     uint32_t b0, uint32_t b1) {
    asm volatile(
        "mma.sync.aligned.m16n8k8.row.col.f32.tf32.tf32.f32 "
        "{%0,%1,%2,%3}, {%4,%5,%6,%7}, {%8,%9}, {%0,%1,%2,%3};"
        : "+f"(c[0]), "+f"(c[1]), "+f"(c[2]), "+f"(c[3])
        : "r"(a[0]), "r"(a[1]), "r"(a[2]), "r"(a[3]), "r"(b0), "r"(b1));
}

// ---------------------------------------------------------------------------
// GEMM1: aff = X @ Y^T - icpt via 3xTF32 mma.sync.
// CTA tile 128x128, 256 threads, warp tile 32(m) x 64(n).
// smem: Xh/Xl/Yh/Yl, each [128][68] (stride 68 -> conflict-free frag loads).
// ---------------------------------------------------------------------------
__global__ __launch_bounds__(256, 1) void k_gemm1_tc(
    const float* __restrict__ X, const float* __restrict__ Yw,
    const float* __restrict__ icpt)
{
    extern __shared__ float sm[];
    float* XhS = sm;
    float* XlS = sm + 128 * 68;
    float* YhS = sm + 2 * 128 * 68;
    float* YlS = sm + 3 * 128 * 68;

    const int tid = threadIdx.x;
    const int r0 = blockIdx.y * 128, c0 = blockIdx.x * 128;

    // staging: load + tf32-split both tiles
    {
        const float4* xs = (const float4*)(X  + (size_t)r0 * D_);
        const float4* ys = (const float4*)(Yw + (size_t)c0 * D_);
        #pragma unroll
        for (int i = 0; i < 8; i++) {
            int f = tid + i * 256;            // 2048 float4
            int r = f >> 4, c4 = (f & 15) * 4;
            float4 h, l;
            split4(xs[f], h, l);
            *(float4*)(XhS + r * 68 + c4) = h;
            *(float4*)(XlS + r * 68 + c4) = l;
            split4(ys[f], h, l);
            *(float4*)(YhS + r * 68 + c4) = h;
            *(float4*)(YlS + r * 68 + c4) = l;
        }
    }
    __syncthreads();

    const int lane = tid & 31, wid = tid >> 5;
    const int wm = (wid & 3) * 32;       // m offset
    const int wn = (wid >> 2) * 64;      // n offset
    const int g = lane >> 2, t = lane & 3;

    float acc[2][8][4];
    #pragma unroll
    for (int mt = 0; mt < 2; mt++)
        #pragma unroll
        for (int nt = 0; nt < 8; nt++)
            #pragma unroll
            for (int q = 0; q < 4; q++) acc[mt][nt][q] = 0.0f;

    #pragma unroll
    for (int ks = 0; ks < 64; ks += 8) {
        uint32_t ah[2][4], al[2][4];
        #pragma unroll
        for (int mt = 0; mt < 2; mt++) {
            const int rb = wm + mt * 16;
            ah[mt][0] = __float_as_uint(XhS[(rb + g)     * 68 + ks + t]);
            ah[mt][1] = __float_as_uint(XhS[(rb + g + 8) * 68 + ks + t]);
            ah[mt][2] = __float_as_uint(XhS[(rb + g)     * 68 + ks + t + 4]);
            ah[mt][3] = __float_as_uint(XhS[(rb + g + 8) * 68 + ks + t + 4]);
            al[mt][0] = __float_as_uint(XlS[(rb + g)     * 68 + ks + t]);
            al[mt][1] = __float_as_uint(XlS[(rb + g + 8) * 68 + ks + t]);
            al[mt][2] = __float_as_uint(XlS[(rb + g)     * 68 + ks + t + 4]);
            al[mt][3] = __float_as_uint(XlS[(rb + g + 8) * 68 + ks + t + 4]);
        }
        #pragma unroll
        for (int nt = 0; nt < 8; nt++) {
            const int cb = wn + nt * 8;
            uint32_t bh0 = __float_as_uint(YhS[(cb + g) * 68 + ks + t]);
            uint32_t bh1 = __float_as_uint(YhS[(cb + g) * 68 + ks + t + 4]);
            uint32_t bl0 = __float_as_uint(YlS[(cb + g) * 68 + ks + t]);
            uint32_t bl1 = __float_as_uint(YlS[(cb + g) * 68 + ks + t + 4]);
            #pragma unroll
            for (int mt = 0; mt < 2; mt++) {
                mma8(acc[mt][nt], ah[mt], bh0, bh1);
                mma8(acc[mt][nt], ah[mt], bl0, bl1);
                mma8(acc[mt][nt], al[mt], bh0, bh1);
            }
        }
    }

    // epilogue: -icpt, store to g_aff, per-row max/min
    float mx[4] = {-CUDART_INF_F, -CUDART_INF_F, -CUDART_INF_F, -CUDART_INF_F};
    float mn[4] = { CUDART_INF_F,  CUDART_INF_F,  CUDART_INF_F,  CUDART_INF_F};

    #pragma unroll
    for (int mt = 0; mt < 2; mt++) {
        #pragma unroll
        for (int nt = 0; nt < 8; nt++) {
            const int c = c0 + wn + nt * 8 + 2 * t;
            float2 ic = *(const float2*)(icpt + c);
            float o0 = acc[mt][nt][0] - ic.x;
            float o1 = acc[mt][nt][1] - ic.y;
            float o2 = acc[mt][nt][2] - ic.x;
            float o3 = acc[mt][nt][3] - ic.y;
            const int re = r0 + wm + mt * 16 + g;
            *(float2*)(g_aff + (size_t)re * K_ + c)       = make_float2(o0, o1);
            *(float2*)(g_aff + (size_t)(re + 8) * K_ + c) = make_float2(o2, o3);
            const int s0 = mt * 2, s1 = mt * 2 + 1;
            mx[s0] = fmaxf(mx[s0], fmaxf(o0, o1));
            mn[s0] = fminf(mn[s0], fminf(o0, o1));
            mx[s1] = fmaxf(mx[s1], fmaxf(o2, o3));
            mn[s1] = fminf(mn[s1], fminf(o2, o3));
        }
    }
    #pragma unroll
    for (int m = 1; m < 4; m <<= 1) {
        #pragma unroll
        for (int s = 0; s < 4; s++) {
            mx[s] = fmaxf(mx[s], __shfl_xor_sync(0xffffffffu, mx[s], m));
            mn[s] = fminf(mn[s], __shfl_xor_sync(0xffffffffu, mn[s], m));
        }
    }
    if (t == 0) {
        #pragma unroll
        for (int mt = 0; mt < 2; mt++) {
            const int re = r0 + wm + mt * 16 + g;
            atomicMax(&g_pmax[re],     encf(mx[mt * 2]));
            atomicMax(&g_nmax[re],     encf(-mn[mt * 2]));
            atomicMax(&g_pmax[re + 8], encf(mx[mt * 2 + 1]));
            atomicMax(&g_nmax[re + 8], encf(-mn[mt * 2 + 1]));
        }
    }
}

// ---------------------------------------------------------------------------
// k_soft: adaptive-temp softmax + v + choice = w @ Y via 3xTF32 mma.sync.
// 128 rows/block, 512 threads: 8 producer warps (load aff, exp, split, Z/v,
// stage Y transposed+split), 8 consumer warps (mma GEMM, 32x32 warp tiles).
// Double-buffered 64-k chunks, named barriers (R3 scheme).
// ---------------------------------------------------------------------------
#define EBUF (128 * 68)
#define YBUF (64 * 68)

__global__ __launch_bounds__(512, 1) void k_soft(
    const float* __restrict__ Yw,
    float* __restrict__ out_choice, float* __restrict__ out_v)
{
    extern __shared__ float sm[];
    // per buf: [Eh | El]; bufs at 0 and 2*EBUF
    float* Ebase = sm;
    float* Ybase = sm + 4 * EBUF;           // per buf: [Yh | Yl]
    float* tS = sm + 4 * EBUF + 4 * YBUF;   // [128]
    float* mS = tS + 128;
    float* Zs = mS + 128;
    float* Vs = Zs + 128;

    const int r0  = blockIdx.x * 128;
    const int tid = threadIdx.x;

    if (tid < 128) {
        float mxv = decf(g_pmax[r0 + tid]);
        float mnv = -decf(g_nmax[r0 + tid]);
        float span = fmaxf(mxv - mnv, 1e-3f);
        tS[tid] = fminf(fmaxf(TEMP_ / span, TEMP_), MAXEFF_);
        mS[tid] = mxv;
    }
    __syncthreads();

    if (tid < 256) {   // ---------------- producers ----------------
        const int prow  = tid >> 1;
        const int phalf = tid & 1;
        const float t_r = tS[prow];
        const float m_r = mS[prow];
        float zacc = 0.0f, vacc = 0.0f;
        const float* arow = g_aff + (size_t)(r0 + prow) * K_ + phalf * 32;

        for (int c = 0; c < K_ / 64; c++) {
            const int buf = c & 1;
            if (c >= 2)
                asm volatile("bar.sync %0, %1;" :: "r"(1 + buf), "r"(512) : "memory");

            // stage Y chunk transposed + split: Yt[d][k], stride 68
            {
                float* yh = Ybase + buf * 2 * YBUF;
                float* yl = yh + YBUF;
                const float4* ysrc = (const float4*)(Yw + (size_t)c * 64 * D_);
                #pragma unroll
                for (int i = 0; i < 4; i++) {
                    int f = tid + i * 256;           // 1024 float4
                    int k = f >> 4, d4 = (f & 15) * 4;
                    float4 h, l;
                    split4(ysrc[f], h, l);
                    yh[(d4 + 0) * 68 + k] = h.x;  yl[(d4 + 0) * 68 + k] = l.x;
                    yh[(d4 + 1) * 68 + k] = h.y;  yl[(d4 + 1) * 68 + k] = l.y;
                    yh[(d4 + 2) * 68 + k] = h.z;  yl[(d4 + 2) * 68 + k] = l.z;
                    yh[(d4 + 3) * 68 + k] = h.w;  yl[(d4 + 3) * 68 + k] = l.w;
                }
            }
            // exp this row's 32 aff values; split to tf32 hi/lo, store row-major
            {
                float* eh = Ebase + buf * 2 * EBUF + prow * 68 + phalf * 32;
                float* el = eh + EBUF;
                const float4* src = (const float4*)(arow + (size_t)c * 64);
                #pragma unroll
                for (int i = 0; i < 8; i++) {
                    float4 a = src[i];
                    float e0 = __expf(t_r * (a.x - m_r));
                    float e1 = __expf(t_r * (a.y - m_r));
                    float e2 = __expf(t_r * (a.z - m_r));
                    float e3 = __expf(t_r * (a.w - m_r));
                    zacc += (e0 + e1) + (e2 + e3);
                    vacc += e0 * a.x + e1 * a.y + e2 * a.z + e3 * a.w;
                    float4 ev = make_float4(e0, e1, e2, e3);
                    float4 h, l;
                    split4(ev, h, l);
                    *(float4*)(eh + i * 4) = h;
                    *(float4*)(el + i * 4) = l;
                }
            }
            asm volatile("bar.arrive %0, %1;" :: "r"(3 + buf), "r"(512) : "memory");
        }

        zacc += __shfl_xor_sync(0xffffffffu, zacc, 1);
        vacc += __shfl_xor_sync(0xffffffffu, vacc, 1);
        if (phalf == 0) { Zs[prow] = zacc; Vs[prow] = vacc; }
        __syncthreads();
        if (tid < 128)
            out_v[r0 + tid] = Vs[tid] / Zs[tid];
    } else {           // ---------------- consumers ----------------
        const int ctid = tid - 256;
        const int lane = ctid & 31, cwid = ctid >> 5;
        const int wm = (cwid & 3) * 32;       // rows
        const int wn = (cwid >> 2) * 32;      // d cols
        const int g = lane >> 2, t = lane & 3;

        float acc[2][4][4];
        #pragma unroll
        for (int mt = 0; mt < 2; mt++)
            #pragma unroll
            for (int nt = 0; nt < 4; nt++)
                #pragma unroll
                for (int q = 0; q < 4; q++) acc[mt][nt][q] = 0.0f;

        for (int c = 0; c < K_ / 64; c++) {
            const int buf = c & 1;
            asm volatile("bar.sync %0, %1;" :: "r"(3 + buf), "r"(512) : "memory");

            const float* eh = Ebase + buf * 2 * EBUF;
            const float* el = eh + EBUF;
            const float* yh = Ybase + buf * 2 * YBUF;
            const float* yl = yh + YBUF;

            #pragma unroll
            for (int ks = 0; ks < 64; ks += 8) {
                uint32_t ah[2][4], al[2][4];
                #pragma unroll
                for (int mt = 0; mt < 2; mt++) {
                    const int rb = wm + mt * 16;
                    ah[mt][0] = __float_as_uint(eh[(rb + g)     * 68 + ks + t]);
                    ah[mt][1] = __float_as_uint(eh[(rb + g + 8) * 68 + ks + t]);
                    ah[mt][2] = __float_as_uint(eh[(rb + g)     * 68 + ks + t + 4]);
                    ah[mt][3] = __float_as_uint(eh[(rb + g + 8) * 68 + ks + t + 4]);
                    al[mt][0] = __float_as_uint(el[(rb + g)     * 68 + ks + t]);
                    al[mt][1] = __float_as_uint(el[(rb + g + 8) * 68 + ks + t]);
                    al[mt][2] = __float_as_uint(el[(rb + g)     * 68 + ks + t + 4]);
                    al[mt][3] = __float_as_uint(el[(rb + g + 8) * 68 + ks + t + 4]);
                }
                #pragma unroll
                for (int nt = 0; nt < 4; nt++) {
                    const int cb = wn + nt * 8;
                    uint32_t bh0 = __float_as_uint(yh[(cb + g) * 68 + ks + t]);
                    uint32_t bh1 = __float_as_uint(yh[(cb + g) * 68 + ks + t + 4]);
                    uint32_t bl0 = __float_as_uint(yl[(cb + g) * 68 + ks + t]);
                    uint32_t bl1 = __float_as_uint(yl[(cb + g) * 68 + ks + t + 4]);
                    #pragma unroll
                    for (int mt = 0; mt < 2; mt++) {
                        mma8(acc[mt][nt], ah[mt], bh0, bh1);
                        mma8(acc[mt][nt], ah[mt], bl0, bl1);
                        mma8(acc[mt][nt], al[mt], bh0, bh1);
                    }
                }
            }
            asm volatile("bar.arrive %0, %1;" :: "r"(1 + buf), "r"(512) : "memory");
        }

        __syncthreads();   // join producers (Zs ready)

        #pragma unroll
        for (int mt = 0; mt < 2; mt++) {
            const int re = wm + mt * 16 + g;
            const float inv0 = 1.0f / Zs[re];
            const float inv1 = 1.0f / Zs[re + 8];
            #pragma unroll
            for (int nt = 0; nt < 4; nt++) {
                const int col = wn + nt * 8 + 2 * t;
                *(float2*)(out_choice + (size_t)(r0 + re) * D_ + col) =
                    make_float2(acc[mt][nt][0] * inv0, acc[mt][nt][1] * inv0);
                *(float2*)(out_choice + (size_t)(r0 + re + 8) * D_ + col) =
                    make_float2(acc[mt][nt][2] * inv1, acc[mt][nt][3] * inv1);
            }
        }
    }
}

// ---------------------------------------------------------------------------
extern "C" void kernel_launch(void* const* d_in, const int* in_sizes, int n_in,
                              void* d_out, int out_size) {
    const float* X    = (const float*)d_in[0];
    const float* Yw   = (const float*)d_in[1];
    const float* icpt = (const float*)d_in[2];
    float* out        = (float*)d_out;
    float* out_choice = out;
    float* out_v      = out + (size_t)S_ * D_;

    const int smemG = 4 * 128 * 68 * 4;                         // 139,264
    const int smemS = (4 * EBUF + 4 * YBUF + 512) * 4;          // 210,944
    cudaFuncSetAttribute(k_gemm1_tc, cudaFuncAttributeMaxDynamicSharedMemorySize, smemG);
    cudaFuncSetAttribute(k_soft,     cudaFuncAttributeMaxDynamicSharedMemorySize, smemS);

    dim3 g1(K_ / 128, S_ / 128);
    k_gemm1_tc<<<g1, 256, smemG>>>(X, Yw, icpt);
    k_soft<<<S_ / 128, 512, smemS>>>(Yw, out_choice, out_v);
}

// round 7
// speedup vs baseline: 1.1754x; 1.1754x over previous
#include <cuda_runtime.h>
#include <cuda_bf16.h>
#include <math_constants.h>
#include <cstdint>

#define S_ 16384
#define K_ 4096
#define D_ 64
#define TEMP_ 50.0f
#define MAXEFF_ 5000.0f

// ---------------- scratch ----------------
__device__ float        g_aff[(size_t)S_ * K_];
__device__ unsigned int g_pmax[S_];
__device__ unsigned int g_nmax[S_];
// Fragment-packed Y splits: {hi(t), hi(t+4), lo(t), lo(t+4)}
__device__ float4 g_Yp1[K_ * 8 * 4];        // [row][d-slab 0..7][t]   (gemm1 B)
__device__ float4 g_Yt2[D_ * (K_ / 8) * 4]; // [d][k-slab 0..511][t]  (gemm2 B, transposed)

__device__ __forceinline__ unsigned int encf(float f) {
    unsigned int u = __float_as_uint(f);
    return (u & 0x80000000u) ? ~u : (u | 0x80000000u);
}
__device__ __forceinline__ float decf(unsigned int u) {
    return (u & 0x80000000u) ? __uint_as_float(u ^ 0x80000000u)
                             : __uint_as_float(~u);
}

// ---------------- tf32 helpers ----------------
__device__ __forceinline__ float tf32r(float x) {
    uint32_t u;
    asm("cvt.rna.tf32.f32 %0, %1;" : "=r"(u) : "f"(x));
    return __uint_as_float(u);
}
__device__ __forceinline__ void split1(float x, float& h, float& l) {
    h = tf32r(x);
    l = tf32r(x - h);
}

__device__ __forceinline__ void mma8(float* c, const uint32_t* a,
                                     uint32_t b0, uint32_t b1) {
    asm volatile(
        "mma.sync.aligned.m16n8k8.row.col.f32.tf32.tf32.f32 "
        "{%0,%1,%2,%3}, {%4,%5,%6,%7}, {%8,%9}, {%0,%1,%2,%3};"
        : "+f"(c[0]), "+f"(c[1]), "+f"(c[2]), "+f"(c[3])
        : "r"(a[0]), "r"(a[1]), "r"(a[2]), "r"(a[3]), "r"(b0), "r"(b1));
}

// ---------------------------------------------------------------------------
// k_prep: build packed hi/lo Y tables (once; replaces per-CTA re-splitting).
// ---------------------------------------------------------------------------
__global__ __launch_bounds__(256) void k_prep(const float* __restrict__ Yw) {
    const int i = blockIdx.x * 256 + threadIdx.x;   // 0..262143
    float y0, y1;
    if (i < K_ * 32) {                     // g_Yp1: r=i>>5, s=(i>>2)&7, t=i&3
        int r = i >> 5, s = (i >> 2) & 7, t = i & 3;
        y0 = Yw[r * D_ + 8 * s + t];
        y1 = Yw[r * D_ + 8 * s + t + 4];
        float h0, l0, h1, l1;
        split1(y0, h0, l0); split1(y1, h1, l1);
        g_Yp1[i] = make_float4(h0, h1, l0, l1);
    } else {                               // g_Yt2: d=j>>11, s=(j>>2)&511, t=j&3
        int j = i - K_ * 32;
        int d = j >> 11, s = (j >> 2) & 511, t = j & 3;
        y0 = Yw[(8 * s + t) * D_ + d];
        y1 = Yw[(8 * s + t + 4) * D_ + d];
        float h0, l0, h1, l1;
        split1(y0, h0, l0); split1(y1, h1, l1);
        g_Yt2[j] = make_float4(h0, h1, l0, l1);
    }
}

// ---------------------------------------------------------------------------
// GEMM1: aff = X @ Y^T - icpt. CTA 128x128, 256 thr.
// 4 row-warps (32 rows, 2 mt) x 2 col-groups (64 cols, 8 nt).
// B staged once from g_Yp1 (pure copy). A: direct LDG + split in regs.
// ---------------------------------------------------------------------------
__global__ __launch_bounds__(256, 1) void k_gemm1_tc(
    const float* __restrict__ X, const float* __restrict__ icpt)
{
    extern __shared__ float4 sb4[];   // B: [128 rows][36 float4] (pad 36)

    const int tid = threadIdx.x;
    const int lane = tid & 31, wid = tid >> 5;
    const int wrow = (wid & 3) * 32;
    const int wn = (wid >> 2) * 64;
    const int g = lane >> 2, t = lane & 3;
    const int r0 = blockIdx.y * 128, c0 = blockIdx.x * 128;

    // stage B: 128 rows x 32 float4, contiguous in g_Yp1
    #pragma unroll
    for (int j = 0; j < 16; j++) {
        int f = tid + j * 256;
        int row = f >> 5, w = f & 31;
        sb4[row * 36 + w] = g_Yp1[(c0 + row) * 32 + w];
    }
    __syncthreads();

    float acc[2][8][4];
    #pragma unroll
    for (int mt = 0; mt < 2; mt++)
        #pragma unroll
        for (int nt = 0; nt < 8; nt++)
            #pragma unroll
            for (int q = 0; q < 4; q++) acc[mt][nt][q] = 0.0f;

    #pragma unroll
    for (int s = 0; s < 8; s++) {
        const int ks = s * 8;
        uint32_t ah[2][4], al[2][4];
        #pragma unroll
        for (int mt = 0; mt < 2; mt++) {
            const float* xr0 = X + (size_t)(r0 + wrow + mt * 16 + g) * D_ + ks;
            const float* xr1 = xr0 + 8 * D_;
            float h, l;
            split1(__ldg(xr0 + t),     h, l); ah[mt][0] = __float_as_uint(h); al[mt][0] = __float_as_uint(l);
            split1(__ldg(xr1 + t),     h, l); ah[mt][1] = __float_as_uint(h); al[mt][1] = __float_as_uint(l);
            split1(__ldg(xr0 + t + 4), h, l); ah[mt][2] = __float_as_uint(h); al[mt][2] = __float_as_uint(l);
            split1(__ldg(xr1 + t + 4), h, l); ah[mt][3] = __float_as_uint(h); al[mt][3] = __float_as_uint(l);
        }
        #pragma unroll
        for (int nt = 0; nt < 8; nt++) {
            uint4 bq = *(const uint4*)&sb4[(wn + nt * 8 + g) * 36 + s * 4 + t];
            #pragma unroll
            for (int mt = 0; mt < 2; mt++) {
                mma8(acc[mt][nt], ah[mt], bq.x, bq.y);   // hh
                mma8(acc[mt][nt], ah[mt], bq.z, bq.w);   // h·lo
                mma8(acc[mt][nt], al[mt], bq.x, bq.y);   // lo·h
            }
        }
    }

    // epilogue
    float mx[4] = {-CUDART_INF_F, -CUDART_INF_F, -CUDART_INF_F, -CUDART_INF_F};
    float mn[4] = { CUDART_INF_F,  CUDART_INF_F,  CUDART_INF_F,  CUDART_INF_F};

    #pragma unroll
    for (int mt = 0; mt < 2; mt++) {
        #pragma unroll
        for (int nt = 0; nt < 8; nt++) {
            const int c = c0 + wn + nt * 8 + 2 * t;
            float2 ic = __ldg((const float2*)(icpt + c));
            float o0 = acc[mt][nt][0] - ic.x;
            float o1 = acc[mt][nt][1] - ic.y;
            float o2 = acc[mt][nt][2] - ic.x;
            float o3 = acc[mt][nt][3] - ic.y;
            const int row = r0 + wrow + mt * 16 + g;
            *(float2*)(g_aff + (size_t)row * K_ + c)       = make_float2(o0, o1);
            *(float2*)(g_aff + (size_t)(row + 8) * K_ + c) = make_float2(o2, o3);
            mx[mt*2]   = fmaxf(mx[mt*2],   fmaxf(o0, o1));
            mn[mt*2]   = fminf(mn[mt*2],   fminf(o0, o1));
            mx[mt*2+1] = fmaxf(mx[mt*2+1], fmaxf(o2, o3));
            mn[mt*2+1] = fminf(mn[mt*2+1], fminf(o2, o3));
        }
    }
    #pragma unroll
    for (int m = 1; m < 4; m <<= 1) {
        #pragma unroll
        for (int i = 0; i < 4; i++) {
            mx[i] = fmaxf(mx[i], __shfl_xor_sync(0xffffffffu, mx[i], m));
            mn[i] = fminf(mn[i], __shfl_xor_sync(0xffffffffu, mn[i], m));
        }
    }
    if (t == 0) {
        #pragma unroll
        for (int mt = 0; mt < 2; mt++) {
            const int row = r0 + wrow + mt * 16 + g;
            atomicMax(&g_pmax[row],     encf(mx[mt*2]));
            atomicMax(&g_nmax[row],     encf(-mn[mt*2]));
            atomicMax(&g_pmax[row + 8], encf(mx[mt*2+1]));
            atomicMax(&g_nmax[row + 8], encf(-mn[mt*2+1]));
        }
    }
}

// ---------------------------------------------------------------------------
// k_soft: adaptive softmax + v + choice = w @ Y.
// CTA 128 rows, 256 thr = 2 k-groups x 4 row-warps (32 rows, 2 mt; 8 nt over d).
// exp+split in registers from direct aff LDG; B chunks prefetched (4 buffers).
// Cross-k-group reduction in smem at the end.
// ---------------------------------------------------------------------------
__global__ __launch_bounds__(256, 1) void k_soft(
    float* __restrict__ out_choice, float* __restrict__ out_v)
{
    extern __shared__ float4 sb4[];   // 4 buffers x 2304 float4 ([64 d][36])

    const int tid = threadIdx.x;
    const int lane = tid & 31, wid = tid >> 5;
    const int grp = wid >> 2;            // k-group 0/1
    const int wrow = (wid & 3) * 32;
    const int g = lane >> 2, t = lane & 3;
    const int r0 = blockIdx.x * 128;

    int rows[4] = {wrow + g, wrow + g + 8, wrow + g + 16, wrow + g + 24};
    float tr[4], mr[4];
    #pragma unroll
    for (int i = 0; i < 4; i++) {
        float mxv = decf(g_pmax[r0 + rows[i]]);
        float mnv = -decf(g_nmax[r0 + rows[i]]);
        float span = fmaxf(mxv - mnv, 1e-3f);
        tr[i] = fminf(fmaxf(TEMP_ / span, TEMP_), MAXEFF_);
        mr[i] = mxv;
    }

    float acc[2][8][4];
    #pragma unroll
    for (int mt = 0; mt < 2; mt++)
        #pragma unroll
        for (int nt = 0; nt < 8; nt++)
            #pragma unroll
            for (int q = 0; q < 4; q++) acc[mt][nt][q] = 0.0f;
    float zv[4] = {0, 0, 0, 0}, vv[4] = {0, 0, 0, 0};

    // stage chunk c into buffer (q, par)
    auto stage = [&](int c, int q, int par) {
        float4* dst = sb4 + (q * 2 + par) * 2304;
        #pragma unroll
        for (int j = 0; j < 8; j++) {
            int f = tid + j * 256;
            int d = f >> 5, w = f & 31;
            dst[d * 36 + w] = g_Yt2[d * 2048 + c * 32 + w];
        }
    };

    stage(0, 0, 0);
    stage(1, 1, 0);
    __syncthreads();

    for (int ss = 0; ss < 32; ss++) {
        const int cur = ss & 1;
        if (ss + 1 < 32) {
            stage(2 * (ss + 1),     0, cur ^ 1);
            stage(2 * (ss + 1) + 1, 1, cur ^ 1);
        }
        const float4* B = sb4 + (grp * 2 + cur) * 2304;
        const int kb = (2 * ss + grp) * 64;

        #pragma unroll 2
        for (int s = 0; s < 8; s++) {
            const int kk = kb + s * 8;
            uint32_t ah[2][4], al[2][4];
            #pragma unroll
            for (int mt = 0; mt < 2; mt++) {
                const float* a0 = g_aff + (size_t)(r0 + rows[mt*2])   * K_ + kk;
                const float* a1 = g_aff + (size_t)(r0 + rows[mt*2+1]) * K_ + kk;
                float x0 = __ldg(a0 + t),     x1 = __ldg(a1 + t);
                float x2 = __ldg(a0 + t + 4), x3 = __ldg(a1 + t + 4);
                float e0 = __expf(tr[mt*2]   * (x0 - mr[mt*2]));
                float e1 = __expf(tr[mt*2+1] * (x1 - mr[mt*2+1]));
                float e2 = __expf(tr[mt*2]   * (x2 - mr[mt*2]));
                float e3 = __expf(tr[mt*2+1] * (x3 - mr[mt*2+1]));
                zv[mt*2]   += e0 + e2;  zv[mt*2+1] += e1 + e3;
                vv[mt*2]   += e0 * x0 + e2 * x2;
                vv[mt*2+1] += e1 * x1 + e3 * x3;
                float h, l;
                split1(e0, h, l); ah[mt][0] = __float_as_uint(h); al[mt][0] = __float_as_uint(l);
                split1(e1, h, l); ah[mt][1] = __float_as_uint(h); al[mt][1] = __float_as_uint(l);
                split1(e2, h, l); ah[mt][2] = __float_as_uint(h); al[mt][2] = __float_as_uint(l);
                split1(e3, h, l); ah[mt][3] = __float_as_uint(h); al[mt][3] = __float_as_uint(l);
            }
            #pragma unroll
            for (int nt = 0; nt < 8; nt++) {
                uint4 bq = *(const uint4*)&B[(nt * 8 + g) * 36 + s * 4 + t];
                #pragma unroll
                for (int mt = 0; mt < 2; mt++) {
                    mma8(acc[mt][nt], ah[mt], bq.x, bq.y);
                    mma8(acc[mt][nt], ah[mt], bq.z, bq.w);
                    mma8(acc[mt][nt], al[mt], bq.x, bq.y);
                }
            }
        }
        __syncthreads();
    }

    // reduce z/v across the 4 t-lanes (butterfly keeps result in all lanes)
    #pragma unroll
    for (int m = 1; m < 4; m <<= 1) {
        #pragma unroll
        for (int i = 0; i < 4; i++) {
            zv[i] += __shfl_xor_sync(0xffffffffu, zv[i], m);
            vv[i] += __shfl_xor_sync(0xffffffffu, vv[i], m);
        }
    }

    // cross-k-group reduction via smem (buffers are dead now)
    float* Rch = (float*)sb4;            // [128][66]
    float* Rz  = (float*)sb4 + 128 * 66;
    float* Rv  = Rz + 128;

    if (grp == 1) {
        #pragma unroll
        for (int mt = 0; mt < 2; mt++)
            #pragma unroll
            for (int nt = 0; nt < 8; nt++) {
                const int row = wrow + mt * 16 + g, col = nt * 8 + 2 * t;
                *(float2*)&Rch[row * 66 + col]       = make_float2(acc[mt][nt][0], acc[mt][nt][1]);
                *(float2*)&Rch[(row + 8) * 66 + col] = make_float2(acc[mt][nt][2], acc[mt][nt][3]);
            }
        if (t == 0) {
            #pragma unroll
            for (int i = 0; i < 4; i++) { Rz[rows[i]] = zv[i]; Rv[rows[i]] = vv[i]; }
        }
    }
    __syncthreads();

    if (grp == 0) {
        float inv[4];
        #pragma unroll
        for (int i = 0; i < 4; i++) {
            float Z = zv[i] + Rz[rows[i]];
            inv[i] = 1.0f / Z;
            if (t == 0) out_v[r0 + rows[i]] = (vv[i] + Rv[rows[i]]) / Z;
        }
        #pragma unroll
        for (int mt = 0; mt < 2; mt++)
            #pragma unroll
            for (int nt = 0; nt < 8; nt++) {
                const int row = wrow + mt * 16 + g, col = nt * 8 + 2 * t;
                float2 p0 = *(const float2*)&Rch[row * 66 + col];
                float2 p1 = *(const float2*)&Rch[(row + 8) * 66 + col];
                *(float2*)(out_choice + (size_t)(r0 + row) * D_ + col) =
                    make_float2((acc[mt][nt][0] + p0.x) * inv[mt*2],
                                (acc[mt][nt][1] + p0.y) * inv[mt*2]);
                *(float2*)(out_choice + (size_t)(r0 + row + 8) * D_ + col) =
                    make_float2((acc[mt][nt][2] + p1.x) * inv[mt*2+1],
                                (acc[mt][nt][3] + p1.y) * inv[mt*2+1]);
            }
    }
}

// ---------------------------------------------------------------------------
extern "C" void kernel_launch(void* const* d_in, const int* in_sizes, int n_in,
                              void* d_out, int out_size) {
    const float* X    = (const float*)d_in[0];
    const float* Yw   = (const float*)d_in[1];
    const float* icpt = (const float*)d_in[2];
    float* out        = (float*)d_out;
    float* out_choice = out;
    float* out_v      = out + (size_t)S_ * D_;

    const int smemG = 128 * 36 * 16;    // 73,728
    const int smemS = 4 * 2304 * 16;    // 147,456
    cudaFuncSetAttribute(k_gemm1_tc, cudaFuncAttributeMaxDynamicSharedMemorySize, smemG);
    cudaFuncSetAttribute(k_soft,     cudaFuncAttributeMaxDynamicSharedMemorySize, smemS);

    k_prep<<<(K_ * 32 + D_ * (K_ / 8) * 4) / 256, 256>>>(Yw);

    dim3 g1(K_ / 128, S_ / 128);
    k_gemm1_tc<<<g1, 256, smemG>>>(X, icpt);
    k_soft<<<S_ / 128, 256, smemS>>>(out_choice, out_v);
}

// round 8
// speedup vs baseline: 1.2110x; 1.0303x over previous
#include <cuda_runtime.h>
#include <cuda_bf16.h>
#include <math_constants.h>
#include <cstdint>

#define S_ 16384
#define K_ 4096
#define D_ 64
#define TEMP_ 50.0f
#define MAXEFF_ 5000.0f

// ---------------- scratch ----------------
__device__ float        g_aff[(size_t)S_ * K_];
__device__ unsigned int g_pmax[S_];
__device__ unsigned int g_nmax[S_];
// Fragment-packed tf32 splits: {hi(t), hi(t+4), lo(t), lo(t+4)}
__device__ float4 g_Yp1[K_ * 8 * 4];        // [row][d-slab][t]      (gemm1 B)
__device__ float4 g_Yt2[D_ * (K_ / 8) * 4]; // [d][k-slab][t]        (gemm2 B, transposed)
__device__ float4 g_Xp[(size_t)S_ * 8 * 4]; // [row][d-slab][t]      (gemm1 A)

__device__ __forceinline__ unsigned int encf(float f) {
    unsigned int u = __float_as_uint(f);
    return (u & 0x80000000u) ? ~u : (u | 0x80000000u);
}
__device__ __forceinline__ float decf(unsigned int u) {
    return (u & 0x80000000u) ? __uint_as_float(u ^ 0x80000000u)
                             : __uint_as_float(~u);
}

// ---------------- tf32 helpers ----------------
__device__ __forceinline__ float tf32r(float x) {
    uint32_t u;
    asm("cvt.rna.tf32.f32 %0, %1;" : "=r"(u) : "f"(x));
    return __uint_as_float(u);
}
__device__ __forceinline__ void split1(float x, float& h, float& l) {
    h = tf32r(x);
    l = tf32r(x - h);
}

__device__ __forceinline__ void mma8(float* c, const uint32_t* a,
                                     uint32_t b0, uint32_t b1) {
    asm volatile(
        "mma.sync.aligned.m16n8k8.row.col.f32.tf32.tf32.f32 "
        "{%0,%1,%2,%3}, {%4,%5,%6,%7}, {%8,%9}, {%0,%1,%2,%3};"
        : "+f"(c[0]), "+f"(c[1]), "+f"(c[2]), "+f"(c[3])
        : "r"(a[0]), "r"(a[1]), "r"(a[2]), "r"(a[3]), "r"(b0), "r"(b1));
}

// ---------------------------------------------------------------------------
// k_prep: build packed hi/lo fragment tables for Y (both GEMMs) and X.
// ---------------------------------------------------------------------------
#define NY1 (K_ * 32)
#define NY2 (D_ * (K_ / 8) * 4)
__global__ __launch_bounds__(256) void k_prep(
    const float* __restrict__ X, const float* __restrict__ Yw)
{
    const int i = blockIdx.x * 256 + threadIdx.x;
    if (i < NY1) {                        // r=i>>5, s=(i>>2)&7, t=i&3
        int r = i >> 5, s = (i >> 2) & 7, t = i & 3;
        float h0, l0, h1, l1;
        split1(Yw[r * D_ + 8 * s + t],     h0, l0);
        split1(Yw[r * D_ + 8 * s + t + 4], h1, l1);
        g_Yp1[i] = make_float4(h0, h1, l0, l1);
    } else if (i < NY1 + NY2) {           // d=j>>11, s=(j>>2)&511, t=j&3
        int j = i - NY1;
        int d = j >> 11, s = (j >> 2) & 511, t = j & 3;
        float h0, l0, h1, l1;
        split1(Yw[(8 * s + t) * D_ + d],     h0, l0);
        split1(Yw[(8 * s + t + 4) * D_ + d], h1, l1);
        g_Yt2[j] = make_float4(h0, h1, l0, l1);
    } else {                              // X table, same layout as Yp1
        int j = i - NY1 - NY2;            // 0 .. S_*32-1
        int r = j >> 5, s = (j >> 2) & 7, t = j & 3;
        float h0, l0, h1, l1;
        split1(X[r * D_ + 8 * s + t],     h0, l0);
        split1(X[r * D_ + 8 * s + t + 4], h1, l1);
        g_Xp[j] = make_float4(h0, h1, l0, l1);
    }
}

// ---------------------------------------------------------------------------
// GEMM1: aff = X @ Y^T - icpt. CTA 128x128, 256 thr. Pure-copy staging of
// BOTH operands from packed tables; inner loop is LDS + mma only.
// ---------------------------------------------------------------------------
__global__ __launch_bounds__(256, 1) void k_gemm1_tc(const float* __restrict__ icpt)
{
    extern __shared__ float4 sm4[];
    float4* As = sm4;                 // [128 rows][36]
    float4* Bs = sm4 + 128 * 36;      // [128 rows][36]

    const int tid = threadIdx.x;
    const int lane = tid & 31, wid = tid >> 5;
    const int wrow = (wid & 3) * 32;
    const int wn = (wid >> 2) * 64;
    const int g = lane >> 2, t = lane & 3;
    const int r0 = blockIdx.y * 128, c0 = blockIdx.x * 128;

    #pragma unroll
    for (int j = 0; j < 16; j++) {
        int f = tid + j * 256;
        int row = f >> 5, w = f & 31;
        As[row * 36 + w] = g_Xp[(size_t)(r0 + row) * 32 + w];
        Bs[row * 36 + w] = g_Yp1[(c0 + row) * 32 + w];
    }
    __syncthreads();

    float acc[2][8][4];
    #pragma unroll
    for (int mt = 0; mt < 2; mt++)
        #pragma unroll
        for (int nt = 0; nt < 8; nt++)
            #pragma unroll
            for (int q = 0; q < 4; q++) acc[mt][nt][q] = 0.0f;

    #pragma unroll
    for (int s = 0; s < 8; s++) {
        uint32_t ah[2][4], al[2][4];
        #pragma unroll
        for (int mt = 0; mt < 2; mt++) {
            const int rb = wrow + mt * 16 + g;
            uint4 q0 = *(const uint4*)&As[rb * 36 + s * 4 + t];
            uint4 q1 = *(const uint4*)&As[(rb + 8) * 36 + s * 4 + t];
            ah[mt][0] = q0.x; ah[mt][1] = q1.x; ah[mt][2] = q0.y; ah[mt][3] = q1.y;
            al[mt][0] = q0.z; al[mt][1] = q1.z; al[mt][2] = q0.w; al[mt][3] = q1.w;
        }
        #pragma unroll
        for (int nt = 0; nt < 8; nt++) {
            uint4 bq = *(const uint4*)&Bs[(wn + nt * 8 + g) * 36 + s * 4 + t];
            #pragma unroll
            for (int mt = 0; mt < 2; mt++) {
                mma8(acc[mt][nt], ah[mt], bq.x, bq.y);
                mma8(acc[mt][nt], ah[mt], bq.z, bq.w);
                mma8(acc[mt][nt], al[mt], bq.x, bq.y);
            }
        }
    }

    // epilogue: -icpt, store aff, per-row max/min
    float mx[4] = {-CUDART_INF_F, -CUDART_INF_F, -CUDART_INF_F, -CUDART_INF_F};
    float mn[4] = { CUDART_INF_F,  CUDART_INF_F,  CUDART_INF_F,  CUDART_INF_F};

    #pragma unroll
    for (int mt = 0; mt < 2; mt++) {
        #pragma unroll
        for (int nt = 0; nt < 8; nt++) {
            const int c = c0 + wn + nt * 8 + 2 * t;
            float2 ic = __ldg((const float2*)(icpt + c));
            float o0 = acc[mt][nt][0] - ic.x;
            float o1 = acc[mt][nt][1] - ic.y;
            float o2 = acc[mt][nt][2] - ic.x;
            float o3 = acc[mt][nt][3] - ic.y;
            const int row = r0 + wrow + mt * 16 + g;
            *(float2*)(g_aff + (size_t)row * K_ + c)       = make_float2(o0, o1);
            *(float2*)(g_aff + (size_t)(row + 8) * K_ + c) = make_float2(o2, o3);
            mx[mt*2]   = fmaxf(mx[mt*2],   fmaxf(o0, o1));
            mn[mt*2]   = fminf(mn[mt*2],   fminf(o0, o1));
            mx[mt*2+1] = fmaxf(mx[mt*2+1], fmaxf(o2, o3));
            mn[mt*2+1] = fminf(mn[mt*2+1], fminf(o2, o3));
        }
    }
    #pragma unroll
    for (int m = 1; m < 4; m <<= 1) {
        #pragma unroll
        for (int i = 0; i < 4; i++) {
            mx[i] = fmaxf(mx[i], __shfl_xor_sync(0xffffffffu, mx[i], m));
            mn[i] = fminf(mn[i], __shfl_xor_sync(0xffffffffu, mn[i], m));
        }
    }
    if (t == 0) {
        #pragma unroll
        for (int mt = 0; mt < 2; mt++) {
            const int row = r0 + wrow + mt * 16 + g;
            atomicMax(&g_pmax[row],     encf(mx[mt*2]));
            atomicMax(&g_nmax[row],     encf(-mn[mt*2]));
            atomicMax(&g_pmax[row + 8], encf(mx[mt*2+1]));
            atomicMax(&g_nmax[row + 8], encf(-mn[mt*2+1]));
        }
    }
}

// ---------------------------------------------------------------------------
// k_soft: adaptive softmax + v + choice = w @ Y.
// 2 k-groups x 4 row-warps; B prefetched (4 buffers); aff loads software-
// pipelined one s-step ahead so DRAM latency hides behind the mma block.
// ---------------------------------------------------------------------------
__global__ __launch_bounds__(256, 1) void k_soft(
    float* __restrict__ out_choice, float* __restrict__ out_v)
{
    extern __shared__ float4 sb4[];   // 4 buffers x 2304 float4 ([64 d][36])

    const int tid = threadIdx.x;
    const int lane = tid & 31, wid = tid >> 5;
    const int grp = wid >> 2;
    const int wrow = (wid & 3) * 32;
    const int g = lane >> 2, t = lane & 3;
    const int r0 = blockIdx.x * 128;

    int rows[4] = {wrow + g, wrow + g + 8, wrow + g + 16, wrow + g + 24};
    float c1r[4], mr[4];
    #pragma unroll
    for (int i = 0; i < 4; i++) {
        float mxv = decf(g_pmax[r0 + rows[i]]);
        float mnv = -decf(g_nmax[r0 + rows[i]]);
        float span = fmaxf(mxv - mnv, 1e-3f);
        float tr = fminf(fmaxf(TEMP_ / span, TEMP_), MAXEFF_);
        c1r[i] = tr * 1.4426950408889634f;   // t * log2(e)
        mr[i] = mxv;
    }

    float acc[2][8][4];
    #pragma unroll
    for (int mt = 0; mt < 2; mt++)
        #pragma unroll
        for (int nt = 0; nt < 8; nt++)
            #pragma unroll
            for (int q = 0; q < 4; q++) acc[mt][nt][q] = 0.0f;
    float zv[4] = {0, 0, 0, 0}, vv[4] = {0, 0, 0, 0};

    auto stage = [&](int c, int q, int par) {
        float4* dst = sb4 + (q * 2 + par) * 2304;
        #pragma unroll
        for (int j = 0; j < 8; j++) {
            int f = tid + j * 256;
            int d = f >> 5, w = f & 31;
            dst[d * 36 + w] = g_Yt2[d * 2048 + c * 32 + w];
        }
    };

    // aff fragment load for step (0..255): xa[mt*4 + {0..3}]
    auto ldx = [&](int step, float* xa) {
        const int kk = (2 * (step >> 3) + grp) * 64 + (step & 7) * 8;
        #pragma unroll
        for (int mt = 0; mt < 2; mt++) {
            const float* a0 = g_aff + (size_t)(r0 + rows[mt*2])   * K_ + kk;
            const float* a1 = g_aff + (size_t)(r0 + rows[mt*2+1]) * K_ + kk;
            xa[mt*4+0] = __ldg(a0 + t);
            xa[mt*4+1] = __ldg(a1 + t);
            xa[mt*4+2] = __ldg(a0 + t + 4);
            xa[mt*4+3] = __ldg(a1 + t + 4);
        }
    };

    stage(0, 0, 0);
    stage(1, 1, 0);

    float xa[8], xb[8];
    ldx(0, xa);
    __syncthreads();

    for (int ss = 0; ss < 32; ss++) {
        const int cur = ss & 1;
        if (ss + 1 < 32) {
            stage(2 * (ss + 1),     0, cur ^ 1);
            stage(2 * (ss + 1) + 1, 1, cur ^ 1);
        }
        const float4* B = sb4 + (grp * 2 + cur) * 2304;

        #pragma unroll
        for (int s = 0; s < 8; s++) {
            const int step = ss * 8 + s;
            if (step + 1 < 256) ldx(step + 1, xb);   // prefetch next s-step

            uint32_t ah[2][4], al[2][4];
            #pragma unroll
            for (int mt = 0; mt < 2; mt++) {
                #pragma unroll
                for (int j = 0; j < 4; j++) {
                    const int ri = mt * 2 + (j & 1);
                    float x = xa[mt*4+j];
                    float e = exp2f((x - mr[ri]) * c1r[ri]);
                    zv[ri] += e;
                    vv[ri] = fmaf(e, x, vv[ri]);
                    float h, l;
                    split1(e, h, l);
                    ah[mt][j] = __float_as_uint(h);
                    al[mt][j] = __float_as_uint(l);
                }
            }
            #pragma unroll
            for (int nt = 0; nt < 8; nt++) {
                uint4 bq = *(const uint4*)&B[(nt * 8 + g) * 36 + s * 4 + t];
                #pragma unroll
                for (int mt = 0; mt < 2; mt++) {
                    mma8(acc[mt][nt], ah[mt], bq.x, bq.y);
                    mma8(acc[mt][nt], ah[mt], bq.z, bq.w);
                    mma8(acc[mt][nt], al[mt], bq.x, bq.y);
                }
            }
            #pragma unroll
            for (int j = 0; j < 8; j++) xa[j] = xb[j];
        }
        __syncthreads();
    }

    // reduce z/v across the 4 t-lanes
    #pragma unroll
    for (int m = 1; m < 4; m <<= 1) {
        #pragma unroll
        for (int i = 0; i < 4; i++) {
            zv[i] += __shfl_xor_sync(0xffffffffu, zv[i], m);
            vv[i] += __shfl_xor_sync(0xffffffffu, vv[i], m);
        }
    }

    // cross-k-group reduction via smem (buffers dead now)
    float* Rch = (float*)sb4;            // [128][66]
    float* Rz  = (float*)sb4 + 128 * 66;
    float* Rv  = Rz + 128;

    if (grp == 1) {
        #pragma unroll
        for (int mt = 0; mt < 2; mt++)
            #pragma unroll
            for (int nt = 0; nt < 8; nt++) {
                const int row = wrow + mt * 16 + g, col = nt * 8 + 2 * t;
                *(float2*)&Rch[row * 66 + col]       = make_float2(acc[mt][nt][0], acc[mt][nt][1]);
                *(float2*)&Rch[(row + 8) * 66 + col] = make_float2(acc[mt][nt][2], acc[mt][nt][3]);
            }
        if (t == 0) {
            #pragma unroll
            for (int i = 0; i < 4; i++) { Rz[rows[i]] = zv[i]; Rv[rows[i]] = vv[i]; }
        }
    }
    __syncthreads();

    if (grp == 0) {
        float inv[4];
        #pragma unroll
        for (int i = 0; i < 4; i++) {
            float Z = zv[i] + Rz[rows[i]];
            inv[i] = 1.0f / Z;
            if (t == 0) out_v[r0 + rows[i]] = (vv[i] + Rv[rows[i]]) / Z;
        }
        #pragma unroll
        for (int mt = 0; mt < 2; mt++)
            #pragma unroll
            for (int nt = 0; nt < 8; nt++) {
                const int row = wrow + mt * 16 + g, col = nt * 8 + 2 * t;
                float2 p0 = *(const float2*)&Rch[row * 66 + col];
                float2 p1 = *(const float2*)&Rch[(row + 8) * 66 + col];
                *(float2*)(out_choice + (size_t)(r0 + row) * D_ + col) =
                    make_float2((acc[mt][nt][0] + p0.x) * inv[mt*2],
                                (acc[mt][nt][1] + p0.y) * inv[mt*2]);
                *(float2*)(out_choice + (size_t)(r0 + row + 8) * D_ + col) =
                    make_float2((acc[mt][nt][2] + p1.x) * inv[mt*2+1],
                                (acc[mt][nt][3] + p1.y) * inv[mt*2+1]);
            }
    }
}

// ---------------------------------------------------------------------------
extern "C" void kernel_launch(void* const* d_in, const int* in_sizes, int n_in,
                              void* d_out, int out_size) {
    const float* X    = (const float*)d_in[0];
    const float* Yw   = (const float*)d_in[1];
    const float* icpt = (const float*)d_in[2];
    float* out        = (float*)d_out;
    float* out_choice = out;
    float* out_v      = out + (size_t)S_ * D_;

    const int smemG = 2 * 128 * 36 * 16;   // 147,456
    const int smemS = 4 * 2304 * 16;       // 147,456
    cudaFuncSetAttribute(k_gemm1_tc, cudaFuncAttributeMaxDynamicSharedMemorySize, smemG);
    cudaFuncSetAttribute(k_soft,     cudaFuncAttributeMaxDynamicSharedMemorySize, smemS);

    const int nprep = NY1 + NY2 + S_ * 32;
    k_prep<<<nprep / 256, 256>>>(X, Yw);

    dim3 g1(K_ / 128, S_ / 128);
    k_gemm1_tc<<<g1, 256, smemG>>>(icpt);
    k_soft<<<S_ / 128, 256, smemS>>>(out_choice, out_v);
}